// round 1
// baseline (speedup 1.0000x reference)
#include <cuda_runtime.h>
#include <cstdint>

#define BB   64
#define DD   2048
#define JJ   196       // 14*14
#define CC   128
#define NCLS 1000

// Output packing (tuple concat, fp32):
//   cpt    [B,C]      @ 0
//   scores [B,NCLS]   @ 8192
//   cpt2   [B,C,1]    @ 72192
//   updates[B,C,D]    @ 80384
#define OFF_SCORES 8192
#define OFF_CPT2   72192
#define OFF_UPD    80384

// Scratch (device globals — no runtime allocation allowed)
__device__ float g_ab [BB * JJ * CC];   // [b][j][c]
__device__ float g_sm [BB * JJ * CC];   // softmax, [b][j][c]
__device__ float g_cpt[BB * CC];        // per-(b,c) softmax sums
__device__ float g_asq[CC];

// ---------------------------------------------------------------------------
// Kernel 0: a_sq[c] = sum_d W_land[c,d]^2  ; also zero g_cpt
// ---------------------------------------------------------------------------
__global__ __launch_bounds__(128) void k_asq(const float* __restrict__ Wl) {
    int c = blockIdx.x;
    int t = threadIdx.x;
    const float* row = Wl + (size_t)c * DD;
    float s = 0.f;
    for (int d = t; d < DD; d += 128) { float v = row[d]; s += v * v; }
    __shared__ float red[4];
    #pragma unroll
    for (int o = 16; o; o >>= 1) s += __shfl_xor_sync(0xffffffffu, s, o);
    if ((t & 31) == 0) red[t >> 5] = s;
    __syncthreads();
    if (t == 0) g_asq[c] = red[0] + red[1] + red[2] + red[3];
    int idx = blockIdx.x * 128 + t;
    if (idx < BB * CC) g_cpt[idx] = 0.f;
}

// ---------------------------------------------------------------------------
// Kernel 1: ab[b][j][c] = sum_d W_land[c][d] * x[b][d][j]
// Block tile: M(C)=128, N(J)=32 (7 tiles cover 196, padded), K-tile 32.
// 256 threads, thread tile 8(M, as 2x4) x 2(N).
// ---------------------------------------------------------------------------
__global__ __launch_bounds__(256) void k_gemm1(const float* __restrict__ x,
                                               const float* __restrict__ Wl) {
    __shared__ float As[32][CC];   // [k][c]
    __shared__ float Bs[32][36];   // [k][j] (+4 pad)

    const int jt  = blockIdx.x;            // 0..6
    const int b   = blockIdx.y;
    const int tid = threadIdx.x;
    const int tm  = tid & 15;              // M group
    const int tn  = tid >> 4;              // N group
    const int j0  = jt * 32;
    const float* xb = x + (size_t)b * DD * JJ;

    float acc[2][4][2];
    #pragma unroll
    for (int g = 0; g < 2; g++)
        #pragma unroll
        for (int i = 0; i < 4; i++) { acc[g][i][0] = 0.f; acc[g][i][1] = 0.f; }

    const int la_c = tid >> 1;             // 0..127
    const int la_h = (tid & 1) * 16;       // 0 / 16
    const int lb_k = tid >> 3;             // 0..31
    const int lb_j = (tid & 7) * 4;        // 0,4,...,28

    for (int k0 = 0; k0 < DD; k0 += 32) {
        // A: W_land[c][k0 + la_h + 0..15]  -> As[k][c]
        const float* arow = Wl + (size_t)la_c * DD + k0 + la_h;
        #pragma unroll
        for (int q = 0; q < 4; q++) {
            float4 v = *(const float4*)(arow + q * 4);
            As[la_h + q * 4 + 0][la_c] = v.x;
            As[la_h + q * 4 + 1][la_c] = v.y;
            As[la_h + q * 4 + 2][la_c] = v.z;
            As[la_h + q * 4 + 3][la_c] = v.w;
        }
        // B: x[b][k0+lb_k][j0+lb_j .. +3]  (J=196 is a multiple of 4 -> whole
        // float4 is either valid or fully OOB)
        {
            int jg = j0 + lb_j;
            float4 v = make_float4(0.f, 0.f, 0.f, 0.f);
            if (jg < JJ) v = *(const float4*)(xb + (size_t)(k0 + lb_k) * JJ + jg);
            Bs[lb_k][lb_j + 0] = v.x;
            Bs[lb_k][lb_j + 1] = v.y;
            Bs[lb_k][lb_j + 2] = v.z;
            Bs[lb_k][lb_j + 3] = v.w;
        }
        __syncthreads();
        #pragma unroll
        for (int k = 0; k < 32; k++) {
            float4 a0 = *(const float4*)&As[k][tm * 4];
            float4 a1 = *(const float4*)&As[k][64 + tm * 4];
            float b0 = Bs[k][tn * 2 + 0];
            float b1 = Bs[k][tn * 2 + 1];
            float av0[4] = {a0.x, a0.y, a0.z, a0.w};
            float av1[4] = {a1.x, a1.y, a1.z, a1.w};
            #pragma unroll
            for (int i = 0; i < 4; i++) {
                acc[0][i][0] += av0[i] * b0;  acc[0][i][1] += av0[i] * b1;
                acc[1][i][0] += av1[i] * b0;  acc[1][i][1] += av1[i] * b1;
            }
        }
        __syncthreads();
    }

    #pragma unroll
    for (int jn = 0; jn < 2; jn++) {
        int jg = j0 + tn * 2 + jn;
        if (jg >= JJ) continue;
        float* dst = g_ab + ((size_t)b * JJ + jg) * CC;
        #pragma unroll
        for (int g = 0; g < 2; g++) {
            float4 o = make_float4(acc[g][0][jn], acc[g][1][jn],
                                   acc[g][2][jn], acc[g][3][jn]);
            *(float4*)(dst + g * 64 + tm * 4) = o;
        }
    }
}

// ---------------------------------------------------------------------------
// Kernel 2: softmax over c of (2*ab - a_sq)   (b_sq cancels in the softmax)
// One warp per (b,j). Also accumulates cpt sums (block-staged atomics).
// ---------------------------------------------------------------------------
__global__ __launch_bounds__(256) void k_softmax() {
    __shared__ float s_asq[CC];
    __shared__ float s_cpt[CC];
    const int tid = threadIdx.x;
    if (tid < CC) { s_asq[tid] = g_asq[tid]; s_cpt[tid] = 0.f; }
    __syncthreads();

    const int b    = blockIdx.y;
    const int j    = blockIdx.x * 8 + (tid >> 5);
    const int lane = tid & 31;

    if (j < JJ) {
        const size_t base = ((size_t)b * JJ + j) * CC;
        float4 av = ((const float4*)(g_ab + base))[lane];
        float l0 = 2.f * av.x - s_asq[lane * 4 + 0];
        float l1 = 2.f * av.y - s_asq[lane * 4 + 1];
        float l2 = 2.f * av.z - s_asq[lane * 4 + 2];
        float l3 = 2.f * av.w - s_asq[lane * 4 + 3];
        float mx = fmaxf(fmaxf(l0, l1), fmaxf(l2, l3));
        #pragma unroll
        for (int o = 16; o; o >>= 1) mx = fmaxf(mx, __shfl_xor_sync(0xffffffffu, mx, o));
        float e0 = __expf(l0 - mx), e1 = __expf(l1 - mx);
        float e2 = __expf(l2 - mx), e3 = __expf(l3 - mx);
        float s = e0 + e1 + e2 + e3;
        #pragma unroll
        for (int o = 16; o; o >>= 1) s += __shfl_xor_sync(0xffffffffu, s, o);
        float r = 1.f / s;
        e0 *= r; e1 *= r; e2 *= r; e3 *= r;
        ((float4*)(g_sm + base))[lane] = make_float4(e0, e1, e2, e3);
        atomicAdd(&s_cpt[lane * 4 + 0], e0);
        atomicAdd(&s_cpt[lane * 4 + 1], e1);
        atomicAdd(&s_cpt[lane * 4 + 2], e2);
        atomicAdd(&s_cpt[lane * 4 + 3], e3);
    }
    __syncthreads();
    if (tid < CC) atomicAdd(&g_cpt[b * CC + tid], s_cpt[tid]);
}

// ---------------------------------------------------------------------------
// Kernel 3: updates[b][c][d] = sum_j g_sm[b][j][c] * x[b][d][j]
// Block tile: M(C)=128, N(D)=128, K(J) padded 196->208, K-tile 16.
// 256 threads, thread tile 8x8.
// ---------------------------------------------------------------------------
__global__ __launch_bounds__(256) void k_gemm2(const float* __restrict__ x,
                                               float* __restrict__ out_upd) {
    __shared__ float As[16][CC];    // [k=j][c]   (g_sm already k-major)
    __shared__ float Bs[16][132];   // [k=j][d] (+4 pad), transposed on load

    const int dt  = blockIdx.x;              // 0..15
    const int b   = blockIdx.y;
    const int tid = threadIdx.x;
    const int tm  = tid & 15;
    const int tn  = tid >> 4;
    const int d0  = dt * 128;
    const float* xb = x + (size_t)b * DD * JJ;
    const float* mb = g_sm + (size_t)b * JJ * CC;

    float acc[8][8];
    #pragma unroll
    for (int i = 0; i < 8; i++)
        #pragma unroll
        for (int jn = 0; jn < 8; jn++) acc[i][jn] = 0.f;

    const int lak = tid >> 4;            // 0..15
    const int lac = (tid & 15) * 8;      // 0..120
    const int lbd = tid >> 1;            // 0..127
    const int lbh = (tid & 1) * 8;       // 0 / 8

    for (int k0 = 0; k0 < 208; k0 += 16) {
        // A: g_sm[b][k0+lak][lac..lac+7] (zero-fill beyond J)
        {
            int kg = k0 + lak;
            float4 v0 = make_float4(0.f,0.f,0.f,0.f), v1 = v0;
            if (kg < JJ) {
                const float* p = mb + (size_t)kg * CC + lac;
                v0 = *(const float4*)(p);
                v1 = *(const float4*)(p + 4);
            }
            *(float4*)&As[lak][lac]     = v0;
            *(float4*)&As[lak][lac + 4] = v1;
        }
        // B: x[b][d0+lbd][k0+lbh + q*4 .. +3] transposed into Bs[k][d]
        #pragma unroll
        for (int q = 0; q < 2; q++) {
            int jg = k0 + lbh + q * 4;
            float4 v = make_float4(0.f,0.f,0.f,0.f);
            if (jg < JJ) v = *(const float4*)(xb + (size_t)(d0 + lbd) * JJ + jg);
            Bs[lbh + q * 4 + 0][lbd] = v.x;
            Bs[lbh + q * 4 + 1][lbd] = v.y;
            Bs[lbh + q * 4 + 2][lbd] = v.z;
            Bs[lbh + q * 4 + 3][lbd] = v.w;
        }
        __syncthreads();
        #pragma unroll
        for (int k = 0; k < 16; k++) {
            float4 a0 = *(const float4*)&As[k][tm * 4];
            float4 a1 = *(const float4*)&As[k][64 + tm * 4];
            float4 b0 = *(const float4*)&Bs[k][tn * 4];
            float4 b1 = *(const float4*)&Bs[k][64 + tn * 4];
            float av[8] = {a0.x,a0.y,a0.z,a0.w, a1.x,a1.y,a1.z,a1.w};
            float bv[8] = {b0.x,b0.y,b0.z,b0.w, b1.x,b1.y,b1.z,b1.w};
            #pragma unroll
            for (int i = 0; i < 8; i++)
                #pragma unroll
                for (int jn = 0; jn < 8; jn++)
                    acc[i][jn] += av[i] * bv[jn];
        }
        __syncthreads();
    }

    #pragma unroll
    for (int i = 0; i < 8; i++) {
        int c = (i < 4) ? (tm * 4 + i) : (64 + tm * 4 + (i - 4));
        float* dst = out_upd + ((size_t)b * CC + c) * DD + d0;
        *(float4*)(dst + tn * 4)      = make_float4(acc[i][0], acc[i][1], acc[i][2], acc[i][3]);
        *(float4*)(dst + 64 + tn * 4) = make_float4(acc[i][4], acc[i][5], acc[i][6], acc[i][7]);
    }
}

// ---------------------------------------------------------------------------
// Kernel 4: finalize cpt (mean), write cpt + cpt2, scores = cpt @ W_cls^T + b
// ---------------------------------------------------------------------------
__global__ __launch_bounds__(256) void k_scores(const float* __restrict__ Wc,
                                                const float* __restrict__ bc,
                                                float* __restrict__ out) {
    __shared__ float s_cpt[CC];
    const int b = blockIdx.x, tid = threadIdx.x;
    if (tid < CC) {
        float v = g_cpt[b * CC + tid] * (1.f / (float)JJ);
        s_cpt[tid] = v;
        out[(size_t)b * CC + tid]            = v;   // cpt
        out[OFF_CPT2 + (size_t)b * CC + tid] = v;   // cpt reshape(b,c,1)
    }
    __syncthreads();
    for (int n = tid; n < NCLS; n += 256) {
        const float4* w = (const float4*)(Wc + (size_t)n * CC);
        float s = 0.f;
        #pragma unroll
        for (int q = 0; q < 32; q++) {
            float4 wv = w[q];
            float4 cv = *(const float4*)&s_cpt[q * 4];
            s += wv.x * cv.x + wv.y * cv.y + wv.z * cv.z + wv.w * cv.w;
        }
        out[OFF_SCORES + (size_t)b * NCLS + n] = s + bc[n];
    }
}

// ---------------------------------------------------------------------------
extern "C" void kernel_launch(void* const* d_in, const int* in_sizes, int n_in,
                              void* d_out, int out_size) {
    const float* x  = (const float*)d_in[0];   // [64,2048,14,14]
    const float* Wl = (const float*)d_in[1];   // [128,2048]
    const float* Wc = (const float*)d_in[2];   // [1000,128]
    const float* bc = (const float*)d_in[3];   // [1000]
    float* out = (float*)d_out;

    k_asq    <<<CC, 128>>>(Wl);
    k_gemm1  <<<dim3(7, BB), 256>>>(x, Wl);
    k_softmax<<<dim3(25, BB), 256>>>();
    k_gemm2  <<<dim3(16, BB), 256>>>(x, out + OFF_UPD);
    k_scores <<<BB, 256>>>(Wc, bc, out);
}

// round 4
// speedup vs baseline: 1.0498x; 1.0498x over previous
#include <cuda_runtime.h>
#include <cstdint>

#define BB   64
#define DD   2048
#define JJ   196       // 14*14
#define CC   128
#define NCLS 1000

// Output packing (tuple concat, fp32):
//   cpt    [B,C]      @ 0
//   scores [B,NCLS]   @ 8192
//   cpt2   [B,C,1]    @ 72192
//   updates[B,C,D]    @ 80384
#define OFF_SCORES 8192
#define OFF_CPT2   72192
#define OFF_UPD    80384

// Scratch (device globals — no runtime allocation allowed)
__device__ float g_ab [BB * JJ * CC];   // [b][j][c]
__device__ float g_sm [BB * JJ * CC];   // softmax, [b][j][c]
__device__ float g_cpt[BB * CC];        // per-(b,c) softmax sums
__device__ float g_asq[CC];

// ---------------------------------------------------------------------------
// Kernel 0: a_sq[c] = sum_d W_land[c,d]^2  ; also zero g_cpt
// ---------------------------------------------------------------------------
__global__ __launch_bounds__(128) void k_asq(const float* __restrict__ Wl) {
    int c = blockIdx.x;
    int t = threadIdx.x;
    const float* row = Wl + (size_t)c * DD;
    float s = 0.f;
    for (int d = t; d < DD; d += 128) { float v = row[d]; s += v * v; }
    __shared__ float red[4];
    #pragma unroll
    for (int o = 16; o; o >>= 1) s += __shfl_xor_sync(0xffffffffu, s, o);
    if ((t & 31) == 0) red[t >> 5] = s;
    __syncthreads();
    if (t == 0) g_asq[c] = red[0] + red[1] + red[2] + red[3];
    int idx = blockIdx.x * 128 + t;
    if (idx < BB * CC) g_cpt[idx] = 0.f;
}

// ---------------------------------------------------------------------------
// Kernel 1: ab[b][j][c] = sum_d W_land[c][d] * x[b][d][j]
// Block tile: M(C)=128, N(J)=32 (7 tiles cover 196, padded), K-tile 32.
// 256 threads, thread tile 8(M, as 2x4) x 2(N).
// ---------------------------------------------------------------------------
__global__ __launch_bounds__(256) void k_gemm1(const float* __restrict__ x,
                                               const float* __restrict__ Wl) {
    __shared__ float As[32][CC];   // [k][c]
    __shared__ float Bs[32][36];   // [k][j] (+4 pad)

    const int jt  = blockIdx.x;            // 0..6
    const int b   = blockIdx.y;
    const int tid = threadIdx.x;
    const int tm  = tid & 15;              // M group
    const int tn  = tid >> 4;              // N group
    const int j0  = jt * 32;
    const float* xb = x + (size_t)b * DD * JJ;

    float acc[2][4][2];
    #pragma unroll
    for (int g = 0; g < 2; g++)
        #pragma unroll
        for (int i = 0; i < 4; i++) { acc[g][i][0] = 0.f; acc[g][i][1] = 0.f; }

    const int la_c = tid >> 1;             // 0..127
    const int la_h = (tid & 1) * 16;       // 0 / 16
    const int lb_k = tid >> 3;             // 0..31
    const int lb_j = (tid & 7) * 4;        // 0,4,...,28

    for (int k0 = 0; k0 < DD; k0 += 32) {
        // A: W_land[c][k0 + la_h + 0..15]  -> As[k][c]
        const float* arow = Wl + (size_t)la_c * DD + k0 + la_h;
        #pragma unroll
        for (int q = 0; q < 4; q++) {
            float4 v = *(const float4*)(arow + q * 4);
            As[la_h + q * 4 + 0][la_c] = v.x;
            As[la_h + q * 4 + 1][la_c] = v.y;
            As[la_h + q * 4 + 2][la_c] = v.z;
            As[la_h + q * 4 + 3][la_c] = v.w;
        }
        // B: x[b][k0+lb_k][j0+lb_j .. +3]  (J=196 is a multiple of 4 -> whole
        // float4 is either valid or fully OOB)
        {
            int jg = j0 + lb_j;
            float4 v = make_float4(0.f, 0.f, 0.f, 0.f);
            if (jg < JJ) v = *(const float4*)(xb + (size_t)(k0 + lb_k) * JJ + jg);
            Bs[lb_k][lb_j + 0] = v.x;
            Bs[lb_k][lb_j + 1] = v.y;
            Bs[lb_k][lb_j + 2] = v.z;
            Bs[lb_k][lb_j + 3] = v.w;
        }
        __syncthreads();
        #pragma unroll
        for (int k = 0; k < 32; k++) {
            float4 a0 = *(const float4*)&As[k][tm * 4];
            float4 a1 = *(const float4*)&As[k][64 + tm * 4];
            float b0 = Bs[k][tn * 2 + 0];
            float b1 = Bs[k][tn * 2 + 1];
            float av0[4] = {a0.x, a0.y, a0.z, a0.w};
            float av1[4] = {a1.x, a1.y, a1.z, a1.w};
            #pragma unroll
            for (int i = 0; i < 4; i++) {
                acc[0][i][0] += av0[i] * b0;  acc[0][i][1] += av0[i] * b1;
                acc[1][i][0] += av1[i] * b0;  acc[1][i][1] += av1[i] * b1;
            }
        }
        __syncthreads();
    }

    #pragma unroll
    for (int jn = 0; jn < 2; jn++) {
        int jg = j0 + tn * 2 + jn;
        if (jg >= JJ) continue;
        float* dst = g_ab + ((size_t)b * JJ + jg) * CC;
        #pragma unroll
        for (int g = 0; g < 2; g++) {
            float4 o = make_float4(acc[g][0][jn], acc[g][1][jn],
                                   acc[g][2][jn], acc[g][3][jn]);
            *(float4*)(dst + g * 64 + tm * 4) = o;
        }
    }
}

// ---------------------------------------------------------------------------
// Kernel 2: softmax over c of (2*ab - a_sq)   (b_sq cancels in the softmax)
// One warp per (b,j). Also accumulates cpt sums (block-staged atomics).
// ---------------------------------------------------------------------------
__global__ __launch_bounds__(256) void k_softmax() {
    __shared__ float s_asq[CC];
    __shared__ float s_cpt[CC];
    const int tid = threadIdx.x;
    if (tid < CC) { s_asq[tid] = g_asq[tid]; s_cpt[tid] = 0.f; }
    __syncthreads();

    const int b    = blockIdx.y;
    const int j    = blockIdx.x * 8 + (tid >> 5);
    const int lane = tid & 31;

    if (j < JJ) {
        const size_t base = ((size_t)b * JJ + j) * CC;
        float4 av = ((const float4*)(g_ab + base))[lane];
        float l0 = 2.f * av.x - s_asq[lane * 4 + 0];
        float l1 = 2.f * av.y - s_asq[lane * 4 + 1];
        float l2 = 2.f * av.z - s_asq[lane * 4 + 2];
        float l3 = 2.f * av.w - s_asq[lane * 4 + 3];
        float mx = fmaxf(fmaxf(l0, l1), fmaxf(l2, l3));
        #pragma unroll
        for (int o = 16; o; o >>= 1) mx = fmaxf(mx, __shfl_xor_sync(0xffffffffu, mx, o));
        float e0 = __expf(l0 - mx), e1 = __expf(l1 - mx);
        float e2 = __expf(l2 - mx), e3 = __expf(l3 - mx);
        float s = e0 + e1 + e2 + e3;
        #pragma unroll
        for (int o = 16; o; o >>= 1) s += __shfl_xor_sync(0xffffffffu, s, o);
        float r = 1.f / s;
        e0 *= r; e1 *= r; e2 *= r; e3 *= r;
        ((float4*)(g_sm + base))[lane] = make_float4(e0, e1, e2, e3);
        atomicAdd(&s_cpt[lane * 4 + 0], e0);
        atomicAdd(&s_cpt[lane * 4 + 1], e1);
        atomicAdd(&s_cpt[lane * 4 + 2], e2);
        atomicAdd(&s_cpt[lane * 4 + 3], e3);
    }
    __syncthreads();
    if (tid < CC) atomicAdd(&g_cpt[b * CC + tid], s_cpt[tid]);
}

// ---------------------------------------------------------------------------
// Kernel 3: updates[b][c][d] = sum_j g_sm[b][j][c] * x[b][d][j]
// Block tile: M(C)=128, N(D)=128, K(J) padded 196->208, K-tile 16.
// 256 threads, thread tile 8x8.
// ---------------------------------------------------------------------------
__global__ __launch_bounds__(256) void k_gemm2(const float* __restrict__ x,
                                               float* __restrict__ out_upd) {
    __shared__ float As[16][CC];    // [k=j][c]   (g_sm already k-major)
    __shared__ float Bs[16][132];   // [k=j][d] (+4 pad), transposed on load

    const int dt  = blockIdx.x;              // 0..15
    const int b   = blockIdx.y;
    const int tid = threadIdx.x;
    const int tm  = tid & 15;
    const int tn  = tid >> 4;
    const int d0  = dt * 128;
    const float* xb = x + (size_t)b * DD * JJ;
    const float* mb = g_sm + (size_t)b * JJ * CC;

    float acc[8][8];
    #pragma unroll
    for (int i = 0; i < 8; i++)
        #pragma unroll
        for (int jn = 0; jn < 8; jn++) acc[i][jn] = 0.f;

    const int lak = tid >> 4;            // 0..15
    const int lac = (tid & 15) * 8;      // 0..120
    const int lbd = tid >> 1;            // 0..127
    const int lbh = (tid & 1) * 8;       // 0 / 8

    for (int k0 = 0; k0 < 208; k0 += 16) {
        // A: g_sm[b][k0+lak][lac..lac+7] (zero-fill beyond J)
        {
            int kg = k0 + lak;
            float4 v0 = make_float4(0.f,0.f,0.f,0.f), v1 = v0;
            if (kg < JJ) {
                const float* p = mb + (size_t)kg * CC + lac;
                v0 = *(const float4*)(p);
                v1 = *(const float4*)(p + 4);
            }
            *(float4*)&As[lak][lac]     = v0;
            *(float4*)&As[lak][lac + 4] = v1;
        }
        // B: x[b][d0+lbd][k0+lbh + q*4 .. +3] transposed into Bs[k][d]
        #pragma unroll
        for (int q = 0; q < 2; q++) {
            int jg = k0 + lbh + q * 4;
            float4 v = make_float4(0.f,0.f,0.f,0.f);
            if (jg < JJ) v = *(const float4*)(xb + (size_t)(d0 + lbd) * JJ + jg);
            Bs[lbh + q * 4 + 0][lbd] = v.x;
            Bs[lbh + q * 4 + 1][lbd] = v.y;
            Bs[lbh + q * 4 + 2][lbd] = v.z;
            Bs[lbh + q * 4 + 3][lbd] = v.w;
        }
        __syncthreads();
        #pragma unroll
        for (int k = 0; k < 16; k++) {
            float4 a0 = *(const float4*)&As[k][tm * 4];
            float4 a1 = *(const float4*)&As[k][64 + tm * 4];
            float4 b0 = *(const float4*)&Bs[k][tn * 4];
            float4 b1 = *(const float4*)&Bs[k][64 + tn * 4];
            float av[8] = {a0.x,a0.y,a0.z,a0.w, a1.x,a1.y,a1.z,a1.w};
            float bv[8] = {b0.x,b0.y,b0.z,b0.w, b1.x,b1.y,b1.z,b1.w};
            #pragma unroll
            for (int i = 0; i < 8; i++)
                #pragma unroll
                for (int jn = 0; jn < 8; jn++)
                    acc[i][jn] += av[i] * bv[jn];
        }
        __syncthreads();
    }

    #pragma unroll
    for (int i = 0; i < 8; i++) {
        int c = (i < 4) ? (tm * 4 + i) : (64 + tm * 4 + (i - 4));
        float* dst = out_upd + ((size_t)b * CC + c) * DD + d0;
        *(float4*)(dst + tn * 4)      = make_float4(acc[i][0], acc[i][1], acc[i][2], acc[i][3]);
        *(float4*)(dst + 64 + tn * 4) = make_float4(acc[i][4], acc[i][5], acc[i][6], acc[i][7]);
    }
}

// ---------------------------------------------------------------------------
// Kernel 4: finalize cpt (mean), write cpt + cpt2, scores = cpt @ W_cls^T + b
// ---------------------------------------------------------------------------
__global__ __launch_bounds__(256) void k_scores(const float* __restrict__ Wc,
                                                const float* __restrict__ bc,
                                                float* __restrict__ out) {
    __shared__ float s_cpt[CC];
    const int b = blockIdx.x, tid = threadIdx.x;
    if (tid < CC) {
        float v = g_cpt[b * CC + tid] * (1.f / (float)JJ);
        s_cpt[tid] = v;
        out[(size_t)b * CC + tid]            = v;   // cpt
        out[OFF_CPT2 + (size_t)b * CC + tid] = v;   // cpt reshape(b,c,1)
    }
    __syncthreads();
    for (int n = tid; n < NCLS; n += 256) {
        const float4* w = (const float4*)(Wc + (size_t)n * CC);
        float s = 0.f;
        #pragma unroll
        for (int q = 0; q < 32; q++) {
            float4 wv = w[q];
            float4 cv = *(const float4*)&s_cpt[q * 4];
            s += wv.x * cv.x + wv.y * cv.y + wv.z * cv.z + wv.w * cv.w;
        }
        out[OFF_SCORES + (size_t)b * NCLS + n] = s + bc[n];
    }
}

// ---------------------------------------------------------------------------
extern "C" void kernel_launch(void* const* d_in, const int* in_sizes, int n_in,
                              void* d_out, int out_size) {
    const float* x  = (const float*)d_in[0];   // [64,2048,14,14]
    const float* Wl = (const float*)d_in[1];   // [128,2048]
    const float* Wc = (const float*)d_in[2];   // [1000,128]
    const float* bc = (const float*)d_in[3];   // [1000]
    float* out = (float*)d_out;

    k_asq    <<<CC, 128>>>(Wl);
    k_gemm1  <<<dim3(7, BB), 256>>>(x, Wl);
    k_softmax<<<dim3(25, BB), 256>>>();
    k_gemm2  <<<dim3(16, BB), 256>>>(x, out + OFF_UPD);
    k_scores <<<BB, 256>>>(Wc, bc, out);
}

// round 8
// speedup vs baseline: 1.9006x; 1.8105x over previous
#include <cuda_runtime.h>
#include <cuda_bf16.h>
#include <mma.h>
#include <cstdint>

using namespace nvcuda;

#define BB   64
#define DD   2048
#define JJ   196
#define CC   128
#define NCLS 1000
#define JP   224        // padded j pitch (7 chunks of 32) for softmax buffers

// Output packing (tuple concat, fp32): cpt | scores | cpt2 | updates
#define OFF_SCORES 8192
#define OFF_CPT2   72192
#define OFF_UPD    80384

// Device-global scratch (static; no runtime allocation)
__device__ __align__(16) __nv_bfloat16 g_Whi[CC * DD];
__device__ __align__(16) __nv_bfloat16 g_Wlo[CC * DD];
__device__ __align__(16) __nv_bfloat16 g_smh[BB * CC * JP];
__device__ __align__(16) __nv_bfloat16 g_sml[BB * CC * JP];
__device__ float g_cpt[BB * CC];
__device__ float g_asq[CC];

__device__ __forceinline__ uint32_t pack2(float a, float b) {
    __nv_bfloat162 p = __floats2bfloat162_rn(a, b);   // a -> low, b -> high
    return *reinterpret_cast<uint32_t*>(&p);
}
__device__ __forceinline__ float bfrnd(float v) {
    return __bfloat162float(__float2bfloat16(v));
}

// ---------------------------------------------------------------------------
// Prep: split W_land into bf16 hi/lo, a_sq[c], zero g_cpt (every launch)
// ---------------------------------------------------------------------------
__global__ __launch_bounds__(128) void k_prep(const float* __restrict__ Wl) {
    const int c = blockIdx.x, t = threadIdx.x;
    const float* row = Wl + (size_t)c * DD;
    float s = 0.f;
    for (int d = t; d < DD; d += 128) {
        float v = row[d];
        float h = bfrnd(v);
        g_Whi[c * DD + d] = __float2bfloat16(h);
        g_Wlo[c * DD + d] = __float2bfloat16(v - h);
        s += v * v;
    }
    __shared__ float red[4];
    #pragma unroll
    for (int o = 16; o; o >>= 1) s += __shfl_xor_sync(0xffffffffu, s, o);
    if ((t & 31) == 0) red[t >> 5] = s;
    __syncthreads();
    if (t == 0) g_asq[c] = red[0] + red[1] + red[2] + red[3];
    if (t < 64) g_cpt[c * 64 + t] = 0.f;
}

// ---------------------------------------------------------------------------
// GEMM1 (wmma bf16 3-term): ab[c][j] = sum_d W[c][d]*x[b][d][j]
// Block: M=128(c) x N=64(j), K=2048 in chunks of 32, double-buffered.
// 8 warps: warp tile 32(c) x 32(j) = 2x2 wmma frags. x is row-major matrix_b.
// Epilogue: logits = 2*ab - asq, softmax over c, split-bf16 -> g_smh/g_sml,
// cpt atomics.
// Buffer layout (bytes): Ah@0 [128][40]bf16=10240, Al@10240,
//   Bh@20480 [32][72]bf16=4608, Bl@25088; buf size 29696, x2 = 59392.
// Epilogue union: logits fp32 [128][68] = 34816.
// ---------------------------------------------------------------------------
#define PA 40
#define PB 72
#define G1_AH 0
#define G1_AL 10240
#define G1_BH 20480
#define G1_BL 25088
#define G1_BUF 29696
#define G1_SMEM 59392
#define LP 68

__global__ __launch_bounds__(256) void k_mma1(const float* __restrict__ x) {
    extern __shared__ char smem[];
    __shared__ float s_asq[CC];
    __shared__ float s_mx[64], s_inv[64];

    const int tid = threadIdx.x, w = tid >> 5;
    const int wm = w & 3, wn = w >> 2;
    const int b = blockIdx.y, j0 = blockIdx.x * 64;
    if (tid < CC) s_asq[tid] = g_asq[tid];

    wmma::fragment<wmma::accumulator, 16, 16, 16, float> acc[2][2];
    #pragma unroll
    for (int i = 0; i < 2; i++)
        #pragma unroll
        for (int j = 0; j < 2; j++) wmma::fill_fragment(acc[i][j], 0.f);

    uint4  fa_h[2], fa_l[2];
    float4 fbv[2];

    auto fetch = [&](int k0) {
        #pragma unroll
        for (int i = 0; i < 2; i++) {
            int u = tid + 256 * i;
            {
                int row = u >> 2, seg = u & 3;
                fa_h[i] = *(const uint4*)(g_Whi + row * DD + k0 + seg * 8);
                fa_l[i] = *(const uint4*)(g_Wlo + row * DD + k0 + seg * 8);
            }
            {
                int kk = u >> 4, jq = u & 15;
                int jg = j0 + jq * 4;
                fbv[i] = make_float4(0.f, 0.f, 0.f, 0.f);
                if (jg < JJ)
                    fbv[i] = *(const float4*)(x + ((size_t)(b * DD + k0 + kk)) * JJ + jg);
            }
        }
    };
    auto commit = [&](char* base) {
        #pragma unroll
        for (int i = 0; i < 2; i++) {
            int u = tid + 256 * i;
            {
                int row = u >> 2, seg = u & 3;
                *(uint4*)(base + G1_AH + row * 80 + seg * 16) = fa_h[i];
                *(uint4*)(base + G1_AL + row * 80 + seg * 16) = fa_l[i];
            }
            {
                int kk = u >> 4, jq = u & 15;
                float4 v = fbv[i];
                float hx = bfrnd(v.x), hy = bfrnd(v.y), hz = bfrnd(v.z), hw = bfrnd(v.w);
                uint2 hi = make_uint2(pack2(hx, hy), pack2(hz, hw));
                uint2 lo = make_uint2(pack2(v.x - hx, v.y - hy), pack2(v.z - hz, v.w - hw));
                *(uint2*)(base + G1_BH + kk * 144 + jq * 8) = hi;
                *(uint2*)(base + G1_BL + kk * 144 + jq * 8) = lo;
            }
        }
    };

    fetch(0);
    commit(smem);
    __syncthreads();

    for (int ch = 0; ch < 64; ch++) {
        char* cbase = smem + (size_t)(ch & 1) * G1_BUF;
        if (ch + 1 < 64) fetch((ch + 1) * 32);

        const __nv_bfloat16* Ah = (const __nv_bfloat16*)(cbase + G1_AH);
        const __nv_bfloat16* Al = (const __nv_bfloat16*)(cbase + G1_AL);
        const __nv_bfloat16* Bh = (const __nv_bfloat16*)(cbase + G1_BH);
        const __nv_bfloat16* Bl = (const __nv_bfloat16*)(cbase + G1_BL);
        #pragma unroll
        for (int ks = 0; ks < 2; ks++) {
            wmma::fragment<wmma::matrix_a, 16, 16, 16, __nv_bfloat16, wmma::row_major> ah[2], al[2];
            wmma::fragment<wmma::matrix_b, 16, 16, 16, __nv_bfloat16, wmma::row_major> bh[2], bl[2];
            #pragma unroll
            for (int i = 0; i < 2; i++) {
                wmma::load_matrix_sync(ah[i], Ah + (wm * 32 + i * 16) * PA + ks * 16, PA);
                wmma::load_matrix_sync(al[i], Al + (wm * 32 + i * 16) * PA + ks * 16, PA);
            }
            #pragma unroll
            for (int j = 0; j < 2; j++) {
                wmma::load_matrix_sync(bh[j], Bh + (ks * 16) * PB + wn * 32 + j * 16, PB);
                wmma::load_matrix_sync(bl[j], Bl + (ks * 16) * PB + wn * 32 + j * 16, PB);
            }
            #pragma unroll
            for (int i = 0; i < 2; i++)
                #pragma unroll
                for (int j = 0; j < 2; j++) {
                    wmma::mma_sync(acc[i][j], ah[i], bh[j], acc[i][j]);
                    wmma::mma_sync(acc[i][j], ah[i], bl[j], acc[i][j]);
                    wmma::mma_sync(acc[i][j], al[i], bh[j], acc[i][j]);
                }
        }

        if (ch + 1 < 64) commit(smem + (size_t)((ch + 1) & 1) * G1_BUF);
        __syncthreads();
    }

    // ---- epilogue: softmax over c ----
    float* lg = (float*)smem;
    #pragma unroll
    for (int i = 0; i < 2; i++)
        #pragma unroll
        for (int j = 0; j < 2; j++)
            wmma::store_matrix_sync(lg + (wm * 32 + i * 16) * LP + wn * 32 + j * 16,
                                    acc[i][j], LP, wmma::mem_row_major);
    __syncthreads();

    if (tid < 64) {
        int j = tid;
        float mx = -1e30f;
        for (int c = 0; c < CC; c++)
            mx = fmaxf(mx, 2.f * lg[c * LP + j] - s_asq[c]);
        float s = 0.f;
        for (int c = 0; c < CC; c++)
            s += __expf(2.f * lg[c * LP + j] - s_asq[c] - mx);
        s_mx[j] = mx;
        s_inv[j] = 1.f / s;
    }
    __syncthreads();

    {
        const int c = tid >> 1, half = tid & 1;
        const float aq = s_asq[c];
        const size_t base = ((size_t)(b * CC) + c) * JP;
        float csum = 0.f;
        #pragma unroll
        for (int jj = 0; jj < 32; jj += 2) {
            int j = half * 32 + jj;
            int jg = j0 + j;
            float p0 = 0.f, p1 = 0.f;
            if (jg < JJ)
                p0 = __expf(2.f * lg[c * LP + j] - aq - s_mx[j]) * s_inv[j];
            if (jg + 1 < JJ)
                p1 = __expf(2.f * lg[c * LP + j + 1] - aq - s_mx[j + 1]) * s_inv[j + 1];
            if (jg < JP) {
                float h0 = bfrnd(p0), h1 = bfrnd(p1);
                *(uint32_t*)&g_smh[base + jg] = pack2(p0, p1);
                *(uint32_t*)&g_sml[base + jg] = pack2(p0 - h0, p1 - h1);
            }
            csum += p0 + p1;
        }
        csum += __shfl_xor_sync(0xffffffffu, csum, 1);
        if (half == 0) atomicAdd(&g_cpt[b * CC + c], csum);
    }
}

// ---------------------------------------------------------------------------
// GEMM2 (wmma bf16 3-term): updates[c][d] = sum_j sm[c][j]*x[b][d][j]
// Block: M=128(c) x N=128(d), K=224 in 7 chunks of 32, double-buffered.
// 8 warps: warp tile 32(c) x 64(d) = 2x4 frags. x is col-major matrix_b
// (element (k=j, n=d) at d*pitch + j). Output stored directly to gmem.
// Buffers: Ah@0 [128][40], Al@10240, Bh@20480 [128 d][40 k], Bl@30720;
// buf 40960 x2 = 81920.
// ---------------------------------------------------------------------------
#define G2_AH 0
#define G2_AL 10240
#define G2_BH 20480
#define G2_BL 30720
#define G2_BUF 40960
#define G2_SMEM 81920

__global__ __launch_bounds__(256) void k_mma2(const float* __restrict__ x,
                                              float* __restrict__ out_upd) {
    extern __shared__ char smem[];
    const int tid = threadIdx.x, w = tid >> 5;
    const int wm = w & 3, wn = w >> 2;
    const int b = blockIdx.y, d0 = blockIdx.x * 128;

    wmma::fragment<wmma::accumulator, 16, 16, 16, float> acc[2][4];
    #pragma unroll
    for (int i = 0; i < 2; i++)
        #pragma unroll
        for (int j = 0; j < 4; j++) wmma::fill_fragment(acc[i][j], 0.f);

    uint4  fa_h[2], fa_l[2];
    float4 fbv[4];

    auto fetch = [&](int k0) {
        #pragma unroll
        for (int i = 0; i < 2; i++) {
            int u = tid + 256 * i;
            int row = u >> 2, seg = u & 3;
            fa_h[i] = *(const uint4*)(g_smh + ((size_t)(b * CC) + row) * JP + k0 + seg * 8);
            fa_l[i] = *(const uint4*)(g_sml + ((size_t)(b * CC) + row) * JP + k0 + seg * 8);
        }
        #pragma unroll
        for (int i = 0; i < 4; i++) {
            int u = tid + 256 * i;
            int row = u >> 3, q = u & 7;
            int jg = k0 + q * 4;
            fbv[i] = make_float4(0.f, 0.f, 0.f, 0.f);
            if (jg < JJ)
                fbv[i] = *(const float4*)(x + ((size_t)(b * DD) + d0 + row) * JJ + jg);
        }
    };
    auto commit = [&](char* base) {
        #pragma unroll
        for (int i = 0; i < 2; i++) {
            int u = tid + 256 * i;
            int row = u >> 2, seg = u & 3;
            *(uint4*)(base + G2_AH + row * 80 + seg * 16) = fa_h[i];
            *(uint4*)(base + G2_AL + row * 80 + seg * 16) = fa_l[i];
        }
        #pragma unroll
        for (int i = 0; i < 4; i++) {
            int u = tid + 256 * i;
            int row = u >> 3, q = u & 7;
            float4 v = fbv[i];
            float hx = bfrnd(v.x), hy = bfrnd(v.y), hz = bfrnd(v.z), hw = bfrnd(v.w);
            uint2 hi = make_uint2(pack2(hx, hy), pack2(hz, hw));
            uint2 lo = make_uint2(pack2(v.x - hx, v.y - hy), pack2(v.z - hz, v.w - hw));
            *(uint2*)(base + G2_BH + row * 80 + q * 8) = hi;
            *(uint2*)(base + G2_BL + row * 80 + q * 8) = lo;
        }
    };

    fetch(0);
    commit(smem);
    __syncthreads();

    for (int ch = 0; ch < 7; ch++) {
        char* cbase = smem + (size_t)(ch & 1) * G2_BUF;
        if (ch + 1 < 7) fetch((ch + 1) * 32);

        const __nv_bfloat16* Ah = (const __nv_bfloat16*)(cbase + G2_AH);
        const __nv_bfloat16* Al = (const __nv_bfloat16*)(cbase + G2_AL);
        const __nv_bfloat16* Bh = (const __nv_bfloat16*)(cbase + G2_BH);
        const __nv_bfloat16* Bl = (const __nv_bfloat16*)(cbase + G2_BL);
        #pragma unroll
        for (int ks = 0; ks < 2; ks++) {
            wmma::fragment<wmma::matrix_a, 16, 16, 16, __nv_bfloat16, wmma::row_major> ah[2], al[2];
            wmma::fragment<wmma::matrix_b, 16, 16, 16, __nv_bfloat16, wmma::col_major> bh[4], bl[4];
            #pragma unroll
            for (int i = 0; i < 2; i++) {
                wmma::load_matrix_sync(ah[i], Ah + (wm * 32 + i * 16) * PA + ks * 16, PA);
                wmma::load_matrix_sync(al[i], Al + (wm * 32 + i * 16) * PA + ks * 16, PA);
            }
            #pragma unroll
            for (int j = 0; j < 4; j++) {
                wmma::load_matrix_sync(bh[j], Bh + (wn * 64 + j * 16) * PA + ks * 16, PA);
                wmma::load_matrix_sync(bl[j], Bl + (wn * 64 + j * 16) * PA + ks * 16, PA);
            }
            #pragma unroll
            for (int i = 0; i < 2; i++)
                #pragma unroll
                for (int j = 0; j < 4; j++) {
                    wmma::mma_sync(acc[i][j], ah[i], bh[j], acc[i][j]);
                    wmma::mma_sync(acc[i][j], ah[i], bl[j], acc[i][j]);
                    wmma::mma_sync(acc[i][j], al[i], bh[j], acc[i][j]);
                }
        }

        if (ch + 1 < 7) commit(smem + (size_t)((ch + 1) & 1) * G2_BUF);
        __syncthreads();
    }

    #pragma unroll
    for (int i = 0; i < 2; i++) {
        int c0 = wm * 32 + i * 16;
        #pragma unroll
        for (int j = 0; j < 4; j++) {
            int dc = d0 + wn * 64 + j * 16;
            wmma::store_matrix_sync(out_upd + ((size_t)(b * CC) + c0) * DD + dc,
                                    acc[i][j], DD, wmma::mem_row_major);
        }
    }
}

// ---------------------------------------------------------------------------
// Finalize: cpt mean, cpt2, scores = cpt @ W_cls^T + b
// ---------------------------------------------------------------------------
__global__ __launch_bounds__(256) void k_scores(const float* __restrict__ Wc,
                                                const float* __restrict__ bc,
                                                float* __restrict__ out) {
    __shared__ float s_cpt[CC];
    const int b = blockIdx.x, tid = threadIdx.x;
    if (tid < CC) {
        float v = g_cpt[b * CC + tid] * (1.f / (float)JJ);
        s_cpt[tid] = v;
        out[(size_t)b * CC + tid]            = v;
        out[OFF_CPT2 + (size_t)b * CC + tid] = v;
    }
    __syncthreads();
    for (int n = tid; n < NCLS; n += 256) {
        const float4* wp = (const float4*)(Wc + (size_t)n * CC);
        float s = 0.f;
        #pragma unroll
        for (int q = 0; q < 32; q++) {
            float4 wv = wp[q];
            float4 cv = *(const float4*)&s_cpt[q * 4];
            s += wv.x * cv.x + wv.y * cv.y + wv.z * cv.z + wv.w * cv.w;
        }
        out[OFF_SCORES + (size_t)b * NCLS + n] = s + bc[n];
    }
}

// ---------------------------------------------------------------------------
extern "C" void kernel_launch(void* const* d_in, const int* in_sizes, int n_in,
                              void* d_out, int out_size) {
    const float* x  = (const float*)d_in[0];
    const float* Wl = (const float*)d_in[1];
    const float* Wc = (const float*)d_in[2];
    const float* bc = (const float*)d_in[3];
    float* out = (float*)d_out;

    cudaFuncSetAttribute(k_mma1, cudaFuncAttributeMaxDynamicSharedMemorySize, G1_SMEM);
    cudaFuncSetAttribute(k_mma2, cudaFuncAttributeMaxDynamicSharedMemorySize, G2_SMEM);

    k_prep  <<<CC, 128>>>(Wl);
    k_mma1  <<<dim3(4, BB), 256, G1_SMEM>>>(x);
    k_mma2  <<<dim3(16, BB), 256, G2_SMEM>>>(x, out + OFF_UPD);
    k_scores<<<BB, 256>>>(Wc, bc, out);
}